// round 1
// baseline (speedup 1.0000x reference)
#include <cuda_runtime.h>

#define LSEQ   2048
#define NBATCH 32
#define GSPLIT 8
#define TPB    128
#define DTC    0.01f

// log2(e) / sqrt(3): fold softmax scale + natural-exp->exp2 conversion into q
#define QSCALE (1.4426950408889634f / 1.7320508075688772f)

__device__ __forceinline__ float ex2(float x) {
    float r;
    asm("ex2.approx.f32 %0, %1;" : "=f"(r) : "f"(x));
    return r;
}

__global__ void __launch_bounds__(TPB) ac_kernel(
    const float* __restrict__ inputs,
    const float* __restrict__ wi,  const float* __restrict__ bi,
    const float* __restrict__ wo,  const float* __restrict__ bo,
    const float* __restrict__ f1w, const float* __restrict__ f1b,
    const float* __restrict__ f2w, const float* __restrict__ f2b,
    const float* __restrict__ g1w, const float* __restrict__ g1b,
    const float* __restrict__ g2w, const float* __restrict__ g2b,
    const float* __restrict__ m1s, const float* __restrict__ m2s,
    const float* __restrict__ sigma,
    float* __restrict__ out)
{
    extern __shared__ float4 skv[];   // [2*LSEQ]: skv[2j]=K_j, skv[2j+1]=V_j
    const int g = blockIdx.x;
    const int b = blockIdx.y;
    const int t = threadIdx.x;

    const float scl0 = sigma[0] + 1e-5f;
    const float scl1 = sigma[1] + 1e-5f;
    const float inv0 = 1.0f / scl0;
    const float inv1 = 1.0f / scl1;
    const float* __restrict__ xb = inputs + (size_t)b * LSEQ * 3;

    // ---------------- Phase A: build K,V for this batch in smem ----------------
    {
        float wk[9], wv[9], bk[3], bv[3];
        #pragma unroll
        for (int i = 0; i < 9; i++) { wk[i] = wi[9 + i]; wv[i] = wi[18 + i]; }
        #pragma unroll
        for (int i = 0; i < 3; i++) { bk[i] = bi[3 + i]; bv[i] = bi[6 + i]; }

        for (int r = t; r < LSEQ; r += TPB) {
            float x0 = xb[3 * r + 0];
            float x1 = xb[3 * r + 1] * inv0;
            float x2 = xb[3 * r + 2] * inv1;
            float k0 = bk[0] + wk[0] * x0 + wk[1] * x1 + wk[2] * x2;
            float k1 = bk[1] + wk[3] * x0 + wk[4] * x1 + wk[5] * x2;
            float k2 = bk[2] + wk[6] * x0 + wk[7] * x1 + wk[8] * x2;
            float v0 = bv[0] + wv[0] * x0 + wv[1] * x1 + wv[2] * x2;
            float v1 = bv[1] + wv[3] * x0 + wv[4] * x1 + wv[5] * x2;
            float v2 = bv[2] + wv[6] * x0 + wv[7] * x1 + wv[8] * x2;
            skv[2 * r + 0] = make_float4(k0, k1, k2, 0.0f);
            skv[2 * r + 1] = make_float4(v0, v1, v2, 0.0f);
        }
    }
    __syncthreads();

    // ---------------- Phase B: two balanced queries per thread ----------------
    // Q-projection weights
    float wq[9], bq[3];
    #pragma unroll
    for (int i = 0; i < 9; i++) wq[i] = wi[i];
    #pragma unroll
    for (int i = 0; i < 3; i++) bq[i] = bi[i];
    // out_proj rows 1,2 (row 0 is masked away by mask_v1)
    float wo1[3] = { wo[3], wo[4], wo[5] };
    float wo2[3] = { wo[6], wo[7], wo[8] };
    float bo1 = bo[1], bo2 = bo[2];
    // epilogue params
    float G10 = g1w[0], G11 = g1w[1], G12 = g1w[2], G1B = g1b[0];
    float G20 = g2w[0], G21 = g2w[1], G22 = g2w[2], G2B = g2b[0];
    float F10 = f1w[0], F11 = f1w[1], F12 = f1w[2], F1B = f1b[0];
    float F20 = f2w[0], F21 = f2w[1], F22 = f2w[2], F2B = f2b[0];
    float M1 = m1s[0], M2 = m2s[0];

    const int p = g * TPB + t;            // pair index 0..1023
    int qidx[2] = { p, LSEQ - 1 - p };

    #pragma unroll
    for (int qq = 0; qq < 2; qq++) {
        const int i = qidx[qq];

        // q for this query (from gmem, L1-hot) — pre-scaled for ex2
        float x0 = xb[3 * i + 0];
        float x1 = xb[3 * i + 1] * inv0;
        float x2 = xb[3 * i + 2] * inv1;
        float q0 = (bq[0] + wq[0] * x0 + wq[1] * x1 + wq[2] * x2) * QSCALE;
        float q1 = (bq[1] + wq[3] * x0 + wq[4] * x1 + wq[5] * x2) * QSCALE;
        float q2 = (bq[2] + wq[6] * x0 + wq[7] * x1 + wq[8] * x2) * QSCALE;

        float den = 0.0f, a0 = 0.0f, a1 = 0.0f, a2 = 0.0f;
        #pragma unroll 4
        for (int j = 0; j <= i; j++) {
            float4 kf = skv[2 * j + 0];
            float s = q0 * kf.x + q1 * kf.y + q2 * kf.z;
            float w = ex2(s);
            float4 vf = skv[2 * j + 1];
            den += w;
            a0 += w * vf.x;
            a1 += w * vf.y;
            a2 += w * vf.z;
        }
        float r = 1.0f / den;
        float c0 = a0 * r, c1 = a1 * r, c2 = a2 * r;

        // out_proj -> S1 = (1, o1, o2)
        float s1 = bo1 + wo1[0] * c0 + wo1[1] * c1 + wo1[2] * c2;
        float s2 = bo2 + wo2[0] * c0 + wo2[1] * c1 + wo2[2] * c2;

        float o[8];
        // S2
        {
            float d1 = (G10 + G11 * s1 + G12 * s2 + G1B) * M1;
            float d2 = (G20 + G21 * s1 + G22 * s2 + G2B) * M2;
            s1 += DTC * d1; s2 += DTC * d2;
            o[0] = s1 * scl0; o[1] = s2 * scl1;
        }
        // S3
        {
            float d1 = (G10 + G11 * s1 + G12 * s2 + G1B) * M1;
            float d2 = (G20 + G21 * s1 + G22 * s2 + G2B) * M2;
            s1 += DTC * d1; s2 += DTC * d2;
            o[2] = s1 * scl0; o[3] = s2 * scl1;
        }
        // S4
        {
            float d1 = (G10 + G11 * s1 + G12 * s2 + G1B) * M1;
            float d2 = (G20 + G21 * s1 + G22 * s2 + G2B) * M2;
            s1 += DTC * d1; s2 += DTC * d2;
            o[4] = s1 * scl0; o[5] = s2 * scl1;
        }
        // out4 = (S4 + v(S4)*dt)*scale, v from f-weights
        {
            float v1 = (F10 + F11 * s1 + F12 * s2 + F1B) * M1;
            float v2 = (F20 + F21 * s1 + F22 * s2 + F2B) * M2;
            o[6] = (s1 + v1 * DTC) * scl0;
            o[7] = (s2 + v2 * DTC) * scl1;
        }

        float4* op = reinterpret_cast<float4*>(out) + ((size_t)(b * LSEQ + i)) * 2;
        op[0] = make_float4(o[0], o[1], o[2], o[3]);
        op[1] = make_float4(o[4], o[5], o[6], o[7]);
    }
}

extern "C" void kernel_launch(void* const* d_in, const int* in_sizes, int n_in,
                              void* d_out, int out_size)
{
    // metadata order: t, inputs, in_proj_w, in_proj_b, out_proj_w, out_proj_b,
    // f1_w, f1_b, f2_w, f2_b, g1_w, g1_b, g2_w, g2_b, m1_s, m2_s, sigma
    const float* inputs = (const float*)d_in[1];
    const float* wi     = (const float*)d_in[2];
    const float* bi     = (const float*)d_in[3];
    const float* wo     = (const float*)d_in[4];
    const float* bo     = (const float*)d_in[5];
    const float* f1w    = (const float*)d_in[6];
    const float* f1b    = (const float*)d_in[7];
    const float* f2w    = (const float*)d_in[8];
    const float* f2b    = (const float*)d_in[9];
    const float* g1w    = (const float*)d_in[10];
    const float* g1b    = (const float*)d_in[11];
    const float* g2w    = (const float*)d_in[12];
    const float* g2b    = (const float*)d_in[13];
    const float* m1s    = (const float*)d_in[14];
    const float* m2s    = (const float*)d_in[15];
    const float* sigma  = (const float*)d_in[16];
    float* out = (float*)d_out;

    const int smem = 2 * LSEQ * (int)sizeof(float4);   // 64 KB
    cudaFuncSetAttribute(ac_kernel, cudaFuncAttributeMaxDynamicSharedMemorySize, smem);

    dim3 grid(GSPLIT, NBATCH);
    ac_kernel<<<grid, TPB, smem>>>(inputs, wi, bi, wo, bo,
                                   f1w, f1b, f2w, f2b,
                                   g1w, g1b, g2w, g2b,
                                   m1s, m2s, sigma, out);
}